// round 3
// baseline (speedup 1.0000x reference)
#include <cuda_runtime.h>
#include <math.h>

#define NMAX 100000
#define EMAX 3200000
#define D 128

// ---------------- scratch (device globals: allocation-guard-safe) ----------
__device__ int   g_deg[NMAX];
__device__ int   g_cursor[NMAX];
__device__ int   g_rowstart[NMAX + 1];
__device__ float g_norm[NMAX];
__device__ int   g_csr_src[EMAX];
__device__ float g_hA[(size_t)NMAX * D];
__device__ float g_hB[(size_t)NMAX * D];
__device__ float g_accum[D];

// ---------------- init: zero degree counters + mean accumulator ------------
__global__ void k_init(int n) {
    int i = blockIdx.x * blockDim.x + threadIdx.x;
    if (i < n) g_deg[i] = 0;
    if (i < D) g_accum[i] = 0.f;
}

// ---------------- degree count ---------------------------------------------
__global__ void k_deg(const int* __restrict__ dst, int e_cnt) {
    int e = blockIdx.x * blockDim.x + threadIdx.x;
    if (e < e_cnt) atomicAdd(&g_deg[dst[e]], 1);
}

// ---------------- norm = clip(deg,1)^-0.5 ----------------------------------
__global__ void k_norm(int n) {
    int i = blockIdx.x * blockDim.x + threadIdx.x;
    if (i < n) {
        float d = (float)g_deg[i];
        if (d < 1.f) d = 1.f;
        g_norm[i] = rsqrtf(d);
    }
}

// ---------------- single-block exclusive scan of degrees -> rowstart -------
__global__ void k_scan(int n, int e_cnt) {
    __shared__ int s[1024];
    int t = threadIdx.x;
    int chunk = (n + 1023) >> 10;
    int lo = t * chunk;
    int hi = lo + chunk; if (hi > n) hi = n;
    int sum = 0;
    for (int i = lo; i < hi; i++) sum += g_deg[i];
    s[t] = sum;
    __syncthreads();
    for (int off = 1; off < 1024; off <<= 1) {
        int v = (t >= off) ? s[t - off] : 0;
        __syncthreads();
        s[t] += v;
        __syncthreads();
    }
    int run = (t == 0) ? 0 : s[t - 1];
    for (int i = lo; i < hi; i++) {
        g_rowstart[i] = run;
        g_cursor[i]   = run;
        run += g_deg[i];
    }
    if (t == 0) g_rowstart[n] = e_cnt;
}

// ---------------- CSR fill (counting-sort by dst) --------------------------
__global__ void k_fill(const int* __restrict__ src, const int* __restrict__ dst, int e_cnt) {
    int e = blockIdx.x * blockDim.x + threadIdx.x;
    if (e < e_cnt) {
        int d = dst[e];
        int pos = atomicAdd(&g_cursor[d], 1);
        g_csr_src[pos] = src[e];
    }
}

// ---------------- propagation: warp per dst node, float4 per lane ----------
__global__ void k_prop(const float* __restrict__ hin, float* __restrict__ hout, int n) {
    int w    = (int)((blockIdx.x * (unsigned)blockDim.x + threadIdx.x) >> 5);
    int lane = threadIdx.x & 31;
    if (w >= n) return;
    int beg = g_rowstart[w];
    int end = g_rowstart[w + 1];
    const float4* __restrict__ h4 = (const float4*)hin;

    float4 a0 = make_float4(0.f, 0.f, 0.f, 0.f);
    float4 a1 = make_float4(0.f, 0.f, 0.f, 0.f);

    int e = beg;
    for (; e + 2 <= end; e += 2) {
        int s0 = g_csr_src[e];
        int s1 = g_csr_src[e + 1];
        float n0 = g_norm[s0];
        float n1 = g_norm[s1];
        float4 v0 = __ldg(&h4[(size_t)s0 * 32 + lane]);
        float4 v1 = __ldg(&h4[(size_t)s1 * 32 + lane]);
        a0.x = fmaf(n0, v0.x, a0.x); a0.y = fmaf(n0, v0.y, a0.y);
        a0.z = fmaf(n0, v0.z, a0.z); a0.w = fmaf(n0, v0.w, a0.w);
        a1.x = fmaf(n1, v1.x, a1.x); a1.y = fmaf(n1, v1.y, a1.y);
        a1.z = fmaf(n1, v1.z, a1.z); a1.w = fmaf(n1, v1.w, a1.w);
    }
    if (e < end) {
        int s0 = g_csr_src[e];
        float n0 = g_norm[s0];
        float4 v0 = __ldg(&h4[(size_t)s0 * 32 + lane]);
        a0.x = fmaf(n0, v0.x, a0.x); a0.y = fmaf(n0, v0.y, a0.y);
        a0.z = fmaf(n0, v0.z, a0.z); a0.w = fmaf(n0, v0.w, a0.w);
    }
    float nn = g_norm[w];
    float4 o;
    o.x = nn * (a0.x + a1.x);
    o.y = nn * (a0.y + a1.y);
    o.z = nn * (a0.z + a1.z);
    o.w = nn * (a0.w + a1.w);
    ((float4*)hout)[(size_t)w * 32 + lane] = o;
}

// ---------------- GEMM + bias + relu: out = relu(h @ W + b) ---------------
// Block: 256 threads, tile = 32 rows x 128 cols. Thread (tx=t&31, ty=t>>5)
// computes 4 rows (ty*4..+3) x 4 cols (tx*4..+3). W cached in dynamic smem.
__global__ void k_gemm_relu(const float* __restrict__ hin,
                            const float* __restrict__ W,
                            const float* __restrict__ bias,
                            float* __restrict__ hout, int n) {
    extern __shared__ float smem[];
    float* sW = smem;            // D*D floats (64 KB)
    float* sh = smem + D * D;    // 32*D floats (16 KB)

    int t  = threadIdx.x;
    int tx = t & 31;
    int ty = t >> 5;
    int rbase = blockIdx.x * 32;

    for (int i = t * 4; i < D * D; i += 256 * 4)
        *(float4*)&sW[i] = *(const float4*)&W[i];

    for (int i = t * 4; i < 32 * D; i += 256 * 4) {
        int r = i >> 7;
        int c = i & (D - 1);
        int row = rbase + r;
        float4 v = make_float4(0.f, 0.f, 0.f, 0.f);
        if (row < n) v = *(const float4*)&hin[(size_t)row * D + c];
        *(float4*)&sh[i] = v;
    }
    __syncthreads();

    float4 bj = *(const float4*)&bias[tx * 4];
    float4 acc[4];
#pragma unroll
    for (int i = 0; i < 4; i++) acc[i] = bj;

#pragma unroll 4
    for (int k = 0; k < D; k++) {
        float4 w = *(float4*)&sW[k * D + tx * 4];
#pragma unroll
        for (int i = 0; i < 4; i++) {
            float hv = sh[(ty * 4 + i) * D + k];
            acc[i].x = fmaf(hv, w.x, acc[i].x);
            acc[i].y = fmaf(hv, w.y, acc[i].y);
            acc[i].z = fmaf(hv, w.z, acc[i].z);
            acc[i].w = fmaf(hv, w.w, acc[i].w);
        }
    }

#pragma unroll
    for (int i = 0; i < 4; i++) {
        int row = rbase + ty * 4 + i;
        if (row < n) {
            float4 o;
            o.x = fmaxf(acc[i].x, 0.f);
            o.y = fmaxf(acc[i].y, 0.f);
            o.z = fmaxf(acc[i].z, 0.f);
            o.w = fmaxf(acc[i].w, 0.f);
            *(float4*)&hout[(size_t)row * D + tx * 4] = o;
        }
    }
}

// ---------------- column mean accumulation ---------------------------------
__global__ void k_mean(const float* __restrict__ h, int n) {
    float sum = 0.f;
    for (int r = blockIdx.x; r < n; r += gridDim.x)
        sum += h[(size_t)r * D + threadIdx.x];
    atomicAdd(&g_accum[threadIdx.x], sum);
}

// ---------------- head: relu(hg@Wf1+bf1) -> relu(@Wf2+bf2) -> sigmoid ------
__global__ void k_head(const float* __restrict__ Wf1, const float* __restrict__ bf1,
                       const float* __restrict__ Wf2, const float* __restrict__ bf2,
                       float* __restrict__ out, float inv_n) {
    __shared__ float hg[D];
    __shared__ float red[D];
    int j = threadIdx.x;  // 128 threads
    hg[j] = g_accum[j] * inv_n;
    __syncthreads();
    float a = bf1[j];
#pragma unroll 4
    for (int k = 0; k < D; k++)
        a = fmaf(hg[k], Wf1[k * D + j], a);
    a = fmaxf(a, 0.f);
    red[j] = a * Wf2[j];
    __syncthreads();
    for (int off = 64; off > 0; off >>= 1) {
        if (j < off) red[j] += red[j + off];
        __syncthreads();
    }
    if (j == 0) {
        float o = fmaxf(red[0] + bf2[0], 0.f);
        out[0] = 1.f / (1.f + expf(-o));
    }
}

// ---------------- launch ----------------------------------------------------
extern "C" void kernel_launch(void* const* d_in, const int* in_sizes, int n_in,
                              void* d_out, int out_size) {
    const float* x   = (const float*)d_in[0];
    const int*   src = (const int*)d_in[1];
    const int*   dst = (const int*)d_in[2];
    const float* W1  = (const float*)d_in[3];
    const float* b1  = (const float*)d_in[4];
    const float* W2  = (const float*)d_in[5];
    const float* b2  = (const float*)d_in[6];
    const float* Wf1 = (const float*)d_in[7];
    const float* bf1 = (const float*)d_in[8];
    const float* Wf2 = (const float*)d_in[9];
    const float* bf2 = (const float*)d_in[10];
    float* out = (float*)d_out;

    int n = in_sizes[0] / D;   // nodes
    int e = in_sizes[1];       // edges

    float *hA = nullptr, *hB = nullptr;
    cudaGetSymbolAddress((void**)&hA, g_hA);
    cudaGetSymbolAddress((void**)&hB, g_hB);

    const int smem_gemm = (D * D + 32 * D) * (int)sizeof(float);  // 80 KB
    cudaFuncSetAttribute(k_gemm_relu, cudaFuncAttributeMaxDynamicSharedMemorySize, smem_gemm);

    int gb_n = (n + 255) / 256;
    int gb_e = (e + 255) / 256;
    int gb_p = (n + 7) / 8;          // 8 warps (nodes) per 256-thread block
    int gb_g = (n + 31) / 32;        // 32 rows per GEMM block

    // ---- CSR build ----
    k_init<<<gb_n, 256>>>(n);
    k_deg<<<gb_e, 256>>>(dst, e);
    k_norm<<<gb_n, 256>>>(n);
    k_scan<<<1, 1024>>>(n, e);
    k_fill<<<gb_e, 256>>>(src, dst, e);

    // ---- propagate K=3 (x -> A -> B -> A) ----
    k_prop<<<gb_p, 256>>>(x,  hA, n);
    k_prop<<<gb_p, 256>>>(hA, hB, n);
    k_prop<<<gb_p, 256>>>(hB, hA, n);

    // ---- relu(h @ W1 + b1): A -> B ----
    k_gemm_relu<<<gb_g, 256, smem_gemm>>>(hA, W1, b1, hB, n);

    // ---- propagate K=3 (B -> A -> B -> A) ----
    k_prop<<<gb_p, 256>>>(hB, hA, n);
    k_prop<<<gb_p, 256>>>(hA, hB, n);
    k_prop<<<gb_p, 256>>>(hB, hA, n);

    // ---- relu(h @ W2 + b2): A -> B ----
    k_gemm_relu<<<gb_g, 256, smem_gemm>>>(hA, W2, b2, hB, n);

    // ---- mean pool + head ----
    k_mean<<<512, D>>>(hB, n);
    k_head<<<1, D>>>(Wf1, bf1, Wf2, bf2, out, 1.0f / (float)n);
}